// round 8
// baseline (speedup 1.0000x reference)
#include <cuda_runtime.h>
#include <cuda_bf16.h>

#define NBX 512
#define NBY 512
#define KK  5
#define TARGET_AREA 0.9f
#define MS  520                     // padded map row stride (floats)
#define MAPSZ (512 * MS + 16)       // max used idx 511*520+515

// ---- static device scratch (no runtime allocation allowed) ----
// M copies: logical (x,y) stored at idx x*MS + (y - k) + 4   (copy k)
// T copies: logical (x,y) stored at idx y*MS + (x - k) + 4   (copy k, transposed)
__device__ __align__(16) float g_M[4][MAPSZ];
__device__ __align__(16) float g_T[4][MAPSZ];
__device__ float g_sum;             // reset by finish's last block
__device__ int   g_done;

__device__ __forceinline__ void red_add_v4(float* a, float v0, float v1, float v2, float v3) {
    asm volatile("red.global.add.v4.f32 [%0], {%1, %2, %3, %4};"
                 :: "l"(a), "f"(v0), "f"(v1), "f"(v2), "f"(v3) : "memory");
}
__device__ __forceinline__ void red_add_f(float* a, float v) {
    asm volatile("red.global.add.f32 [%0], %1;" :: "l"(a), "f"(v) : "memory");
}

// 5 bell-potential values over window starting at s0 (zeros only at the ends)
__device__ __forceinline__ void pot5(float coord, float s, int s0, float* p) {
    float ctr = coord + 0.5f * s;
    float a   = 4.0f / ((s + 2.0f) * (s + 4.0f));
    float cb  = s * (2.0f / (s + 4.0f));
    float p1  = 0.5f * s + 1.0f;
    float p2  = 0.5f * s + 2.0f;
    float d0  = ctr - ((float)s0 + 0.5f);
#pragma unroll
    for (int k = 0; k < KK; k++) {
        float d = fabsf(d0 - (float)k);
        float v;
        if (d < p1)      v = s * (1.0f - a * d * d);
        else if (d < p2) { float t = d - p2; v = cb * t * t; }
        else             v = 0.0f;
        p[k] = v;
    }
}

// strip leading zeros from q[0..4] (shifting zeros in at the top); returns shift
__device__ __forceinline__ int strip5(float* q) {
    int sft = 0;
#pragma unroll
    for (int t = 0; t < 4; t++) {
        if (q[0] == 0.0f) {
            q[0] = q[1]; q[1] = q[2]; q[2] = q[3]; q[3] = q[4]; q[4] = 0.0f;
            sft++;
        }
    }
    return sft;
}

// ---------------------------------------------------------------------------
// Scatter: per node, <=5 row-v4 REDs + (P=.5) column T-v4 + (P=.25) corner
// ---------------------------------------------------------------------------
__global__ void __launch_bounds__(256) scatter_kernel(
    const float* __restrict__ pos,
    const float* __restrict__ sxs,
    const float* __restrict__ sys,
    int n)
{
    int i = blockIdx.x * blockDim.x + threadIdx.x;
    if (i >= n) return;

    float x  = pos[i];
    float y  = pos[n + i];
    float sx = sxs[i];
    float sy = sys[i];

    int sx0 = min(max((int)floorf(x - 2.0f), 0), NBX - KK);
    int sy0 = min(max((int)floorf(y - 2.0f), 0), NBY - KK);

    float px[KK], py[KK];
    pot5(x, sx, sx0, px);
    pot5(y, sy, sy0, py);

    // strip y window; q[0..3] = v4 lanes; q[4] = leftover 5th column (0 if width<5)
    float q[KK] = {py[0], py[1], py[2], py[3], py[4]};
    int ys = sy0 + strip5(q);
    float colv = q[4];                 // nonzero only when shift==0 && width==5
    float* Mk = g_M[ys & 3];
    int ycol = (ys & ~3) + 4;          // aligned offset inside copy (ys&3)

#pragma unroll
    for (int r = 0; r < KK; r++) {
        float vx = px[r];
        if (vx != 0.0f)
            red_add_v4(Mk + (sx0 + r) * MS + ycol,
                       vx * q[0], vx * q[1], vx * q[2], vx * q[3]);
    }

    if (colv != 0.0f) {                // 5th column at logical y = sy0+4
        float c[KK] = {px[0], px[1], px[2], px[3], px[4]};
        int xs = sx0 + strip5(c);
        float corner = c[4];           // nonzero only when shift==0 && width==5
        float* Tk = g_T[xs & 3];
        red_add_v4(Tk + (sy0 + 4) * MS + (xs & ~3) + 4,
                   colv * c[0], colv * c[1], colv * c[2], colv * c[3]);
        if (corner != 0.0f)            // corner (sx0+4, sy0+4)
            red_add_f(&g_M[0][(sx0 + 4) * MS + (sy0 + 4) + 4], corner * colv);
    }
}

// ---------------------------------------------------------------------------
// Finish: density(x,y) = initial + sum(4 M copies) + sum(4 T copies via smem
// transpose); cost = sum((density - target)^2). 1024 blocks, one 16x16 tile
// each (1 cell/thread) for 4x the parallelism of the 32x32 version.
// Zeroing is a separate phase (own-region only: no race, no load/store pairing).
// ---------------------------------------------------------------------------
__global__ void __launch_bounds__(256) finish_kernel(
    const float* __restrict__ initial,
    float* __restrict__ out)
{
    __shared__ float ts[16][17];       // [y-local][x-local], stride 17: conflict-free
    __shared__ float sd[8];

    int b   = blockIdx.x;              // 32 x 32 tiles of 16x16
    int X0  = (b & 31) << 4;
    int Y0  = (b >> 5) << 4;
    int tid = threadIdx.x;
    int tx  = tid & 15;
    int ty  = tid >> 4;                // 0..15

    // Phase 1: fold T copies (T-native coalesced along x; loads only)
    {
        int yg = Y0 + ty;
        float s = 0.0f;
#pragma unroll
        for (int k = 0; k < 4; k++)
            s += g_T[k][yg * MS + (X0 + tx - k + 4)];
        ts[ty][tx] = s;
    }
    __syncthreads();

    // Phase 2: per-cell density (M-native coalesced along y; loads only)
    float acc;
    {
        int xg = X0 + ty;
        int yg = Y0 + tx;
        float v = initial[xg * NBY + yg] + ts[tx][ty];
#pragma unroll
        for (int k = 0; k < 4; k++)
            v += g_M[k][xg * MS + (yg - k + 4)];
        float d = v - TARGET_AREA;
        acc = d * d;
    }

    // Phase 3: zero own region (plain streaming stores)
    {
        int yg = Y0 + ty;
#pragma unroll
        for (int k = 0; k < 4; k++)
            g_T[k][yg * MS + (X0 + tx - k + 4)] = 0.0f;
        int xg = X0 + ty;
#pragma unroll
        for (int k = 0; k < 4; k++)
            g_M[k][xg * MS + (Y0 + tx - k + 4)] = 0.0f;
    }

    // Block reduce + ticketed final write / state reset
    int lane = tid & 31;
    int grp  = tid >> 5;
#pragma unroll
    for (int off = 16; off > 0; off >>= 1)
        acc += __shfl_xor_sync(0xFFFFFFFF, acc, off);
    if (lane == 0) sd[grp] = acc;
    __syncthreads();
    if (tid < 8) {
        float v = sd[tid];
#pragma unroll
        for (int off = 4; off > 0; off >>= 1)
            v += __shfl_xor_sync(0xFF, v, off);
        if (tid == 0) {
            atomicAdd(&g_sum, v);
            __threadfence();
            int t = atomicAdd(&g_done, 1);
            if (t == (int)gridDim.x - 1) {
                out[0] = g_sum;
                g_sum  = 0.0f;         // restore invariants for next replay
                g_done = 0;
            }
        }
    }
}

// ---------------------------------------------------------------------------
extern "C" void kernel_launch(void* const* d_in, const int* in_sizes, int n_in,
                              void* d_out, int out_size) {
    const float* pos = (const float*)d_in[0];
    const float* sx  = (const float*)d_in[1];
    const float* sy  = (const float*)d_in[2];
    // d_in[3..8]: ax..cy — recomputed analytically; d_in[9..10]: bin centers — analytic
    const float* initial = (const float*)d_in[11];
    float* out = (float*)d_out;

    int n = in_sizes[1];

    scatter_kernel<<<(n + 255) / 256, 256>>>(pos, sx, sy, n);
    finish_kernel<<<1024, 256>>>(initial, out);
}

// round 9
// speedup vs baseline: 1.0779x; 1.0779x over previous
#include <cuda_runtime.h>
#include <cuda_bf16.h>

#define NBX 512
#define NBY 512
#define KK  5
#define TARGET_AREA 0.9f
#define MS  520                     // padded map row stride (floats)
#define MAPSZ (512 * MS + 16)       // max used idx 511*520+515

// ---- static device scratch (no runtime allocation allowed) ----
// M copies: logical (x,y) stored at idx x*MS + (y - k) + 4   (copy k)
// T copies: logical (x,y) stored at idx y*MS + (x - k) + 4   (copy k, transposed)
__device__ __align__(16) float g_M[4][MAPSZ];
__device__ __align__(16) float g_T[4][MAPSZ];
__device__ float g_sum;             // reset by finish's last block
__device__ int   g_done;

__device__ __forceinline__ void red_add_v4(float* a, float v0, float v1, float v2, float v3) {
    asm volatile("red.global.add.v4.f32 [%0], {%1, %2, %3, %4};"
                 :: "l"(a), "f"(v0), "f"(v1), "f"(v2), "f"(v3) : "memory");
}
__device__ __forceinline__ void red_add_f(float* a, float v) {
    asm volatile("red.global.add.f32 [%0], %1;" :: "l"(a), "f"(v) : "memory");
}

// 5 bell-potential values over window starting at s0 (zeros only at the ends)
__device__ __forceinline__ void pot5(float coord, float s, int s0, float* p) {
    float ctr = coord + 0.5f * s;
    float a   = 4.0f / ((s + 2.0f) * (s + 4.0f));
    float cb  = s * (2.0f / (s + 4.0f));
    float p1  = 0.5f * s + 1.0f;
    float p2  = 0.5f * s + 2.0f;
    float d0  = ctr - ((float)s0 + 0.5f);
#pragma unroll
    for (int k = 0; k < KK; k++) {
        float d = fabsf(d0 - (float)k);
        float v;
        if (d < p1)      v = s * (1.0f - a * d * d);
        else if (d < p2) { float t = d - p2; v = cb * t * t; }
        else             v = 0.0f;
        p[k] = v;
    }
}

// strip leading zeros from q[0..4] (shifting zeros in at the top); returns shift
__device__ __forceinline__ int strip5(float* q) {
    int sft = 0;
#pragma unroll
    for (int t = 0; t < 4; t++) {
        if (q[0] == 0.0f) {
            q[0] = q[1]; q[1] = q[2]; q[2] = q[3]; q[3] = q[4]; q[4] = 0.0f;
            sft++;
        }
    }
    return sft;
}

// ---------------------------------------------------------------------------
// Scatter: per node, <=5 row-v4 REDs + (P=.5) column T-v4 + (P=.25) corner
// ---------------------------------------------------------------------------
__global__ void __launch_bounds__(256) scatter_kernel(
    const float* __restrict__ pos,
    const float* __restrict__ sxs,
    const float* __restrict__ sys,
    int n)
{
    int i = blockIdx.x * blockDim.x + threadIdx.x;
    if (i >= n) return;

    float x  = pos[i];
    float y  = pos[n + i];
    float sx = sxs[i];
    float sy = sys[i];

    int sx0 = min(max((int)floorf(x - 2.0f), 0), NBX - KK);
    int sy0 = min(max((int)floorf(y - 2.0f), 0), NBY - KK);

    float px[KK], py[KK];
    pot5(x, sx, sx0, px);
    pot5(y, sy, sy0, py);

    // strip y window; q[0..3] = v4 lanes; q[4] = leftover 5th column (0 if width<5)
    float q[KK] = {py[0], py[1], py[2], py[3], py[4]};
    int ys = sy0 + strip5(q);
    float colv = q[4];                 // nonzero only when shift==0 && width==5
    float* Mk = g_M[ys & 3];
    int ycol = (ys & ~3) + 4;          // aligned offset inside copy (ys&3)

#pragma unroll
    for (int r = 0; r < KK; r++) {
        float vx = px[r];
        if (vx != 0.0f)
            red_add_v4(Mk + (sx0 + r) * MS + ycol,
                       vx * q[0], vx * q[1], vx * q[2], vx * q[3]);
    }

    if (colv != 0.0f) {                // 5th column at logical y = sy0+4
        float c[KK] = {px[0], px[1], px[2], px[3], px[4]};
        int xs = sx0 + strip5(c);
        float corner = c[4];           // nonzero only when shift==0 && width==5
        float* Tk = g_T[xs & 3];
        red_add_v4(Tk + (sy0 + 4) * MS + (xs & ~3) + 4,
                   colv * c[0], colv * c[1], colv * c[2], colv * c[3]);
        if (corner != 0.0f)            // corner (sx0+4, sy0+4)
            red_add_f(&g_M[0][(sx0 + 4) * MS + (sy0 + 4) + 4], corner * colv);
    }
}

// ---------------------------------------------------------------------------
// Finish: density(x,y) = initial + sum(4 M copies) + sum(4 T copies via smem
// transpose); cost = sum((density - target)^2).
// 256 blocks x 1024 threads: one 32x32 tile per block, ONE cell per thread,
// every global access 32-wide warp-coalesced (R7 geometry, 4x threads).
// Zeroing is a separate phase (own-region only: no race, no load/store pairing).
// ---------------------------------------------------------------------------
__global__ void __launch_bounds__(1024) finish_kernel(
    const float* __restrict__ initial,
    float* __restrict__ out)
{
    __shared__ float ts[32][33];       // stride 33: conflict-free both ways
    __shared__ float sd[32];

    int b    = blockIdx.x;
    int X0   = (b & 15) << 5;
    int Y0   = (b >> 4) << 5;
    int tid  = threadIdx.x;
    int lane = tid & 31;
    int row  = tid >> 5;               // 0..31 (warp id = local row)

    // Phase 1: fold T copies into smem (T-native: 32-wide along x; loads only)
    {
        int yg = Y0 + row;
        float s = 0.0f;
#pragma unroll
        for (int k = 0; k < 4; k++)
            s += g_T[k][yg * MS + (X0 + lane - k + 4)];
        ts[row][lane] = s;
    }
    __syncthreads();

    // Phase 2: per-cell density (M-native: 32-wide along y; loads only)
    float acc;
    {
        int xg = X0 + row;
        int yg = Y0 + lane;
        float v = initial[xg * NBY + yg] + ts[lane][row];
#pragma unroll
        for (int k = 0; k < 4; k++)
            v += g_M[k][xg * MS + (yg - k + 4)];
        float d = v - TARGET_AREA;
        acc = d * d;
    }

    // Phase 3: zero own region (plain streaming stores, 32-wide)
    {
        int yg = Y0 + row;
#pragma unroll
        for (int k = 0; k < 4; k++)
            g_T[k][yg * MS + (X0 + lane - k + 4)] = 0.0f;
        int xg = X0 + row;
#pragma unroll
        for (int k = 0; k < 4; k++)
            g_M[k][xg * MS + (Y0 + lane - k + 4)] = 0.0f;
    }

    // Block reduce (32 warps) + ticketed final write / state reset
#pragma unroll
    for (int off = 16; off > 0; off >>= 1)
        acc += __shfl_xor_sync(0xFFFFFFFF, acc, off);
    if (lane == 0) sd[row] = acc;
    __syncthreads();
    if (tid < 32) {
        float v = sd[tid];
#pragma unroll
        for (int off = 16; off > 0; off >>= 1)
            v += __shfl_xor_sync(0xFFFFFFFF, v, off);
        if (tid == 0) {
            atomicAdd(&g_sum, v);
            __threadfence();
            int t = atomicAdd(&g_done, 1);
            if (t == (int)gridDim.x - 1) {
                out[0] = g_sum;
                g_sum  = 0.0f;         // restore invariants for next replay
                g_done = 0;
            }
        }
    }
}

// ---------------------------------------------------------------------------
extern "C" void kernel_launch(void* const* d_in, const int* in_sizes, int n_in,
                              void* d_out, int out_size) {
    const float* pos = (const float*)d_in[0];
    const float* sx  = (const float*)d_in[1];
    const float* sy  = (const float*)d_in[2];
    // d_in[3..8]: ax..cy — recomputed analytically; d_in[9..10]: bin centers — analytic
    const float* initial = (const float*)d_in[11];
    float* out = (float*)d_out;

    int n = in_sizes[1];

    scatter_kernel<<<(n + 255) / 256, 256>>>(pos, sx, sy, n);
    finish_kernel<<<256, 1024>>>(initial, out);
}